// round 7
// baseline (speedup 1.0000x reference)
#include <cuda_runtime.h>
#include <math.h>

// Problem constants
#define B 32
#define L 4096
#define H 1024
#define GRID 148            // == SM count -> every block resident in wave 1
#define NTH 1024
#define CHUNK 8
#define NCH (L / CHUNK)     // 512 chunks per b

// Scratch (device globals — no allocation allowed)
__device__ float    g_vpart[32][B * H];    // 4 MB GEMM partials
__device__ float    g_v[B * H];            // 128 KB  v = hid @ W
__device__ float    g_energies[B * L];     // 512 KB
__device__ float2   g_cstats[B * NCH];     // per-chunk (max, sumexp) — slot keyed by chunk -> deterministic
__device__ unsigned g_tick[B];             // work-stealing tickets (reset each replay in P0)
__device__ unsigned g_barctr[3];           // monotonic grid-barrier counters (never reset)

// Grid barrier: monotonic counter, safe across graph replays (no reset).
// All blocks of one replay get tickets in [r*GRID, (r+1)*GRID) -> same target.
__device__ __forceinline__ void grid_barrier(int site)
{
    __syncthreads();
    if (threadIdx.x == 0) {
        __threadfence();
        unsigned t = atomicAdd(&g_barctr[site], 1u);
        unsigned target = (t / GRID + 1u) * GRID;
        unsigned v;
        do {
            asm volatile("ld.acquire.gpu.u32 %0, [%1];"
                         : "=r"(v) : "l"(&g_barctr[site]));
        } while (v < target);
    }
    __syncthreads();
}

extern __shared__ float4 sv[];   // dynamic smem: 8192 float4 = 128 KB, all 32 v rows

__global__ void __launch_bounds__(NTH, 1)
k_fused(const float* __restrict__ hid, const float* __restrict__ enc,
        const float* __restrict__ W, float* __restrict__ out)
{
    __shared__ float  sh_hid[32][33];   // P0 hid tile (padded)
    __shared__ float2 s_st[512];        // P2 stat tree

    const int tid  = threadIdx.x;
    const int blk  = blockIdx.x;
    const int wid  = tid >> 5;
    const int lane = tid & 31;

    // ---------------- P0a: GEMM partials + ticket reset -------------------
    if (blk == GRID - 1 && tid < B) g_tick[tid] = 0;   // ordered by barrier 0

    if (blk < 128) {
        const int g0 = (blk & 31) * 32;                 // g-chunk
        const int h  = (blk >> 5) * 256 + (tid & 255);  // h quarter
        const int b0 = (tid >> 8) * 8;                  // 8-b subgroup

        { // stage hid[b][g0..g0+32] tile (1024 elems, one per thread)
            int bb = tid >> 5, gi = tid & 31;
            sh_hid[bb][gi] = hid[bb * H + g0 + gi];
        }
        __syncthreads();

        float acc[8];
#pragma unroll
        for (int k = 0; k < 8; k++) acc[k] = 0.f;

#pragma unroll 4
        for (int gi = 0; gi < 32; gi++) {
            const float w = W[(size_t)(g0 + gi) * H + h];
#pragma unroll
            for (int k = 0; k < 8; k++)
                acc[k] = fmaf(sh_hid[b0 + k][gi], w, acc[k]);
        }
#pragma unroll
        for (int k = 0; k < 8; k++)
            g_vpart[blk & 31][(size_t)(b0 + k) * H + h] = acc[k];
    }
    grid_barrier(0);

    // ---------------- P0b: deterministic reduce to g_v --------------------
    if (blk < 32) {
        const int i = blk * NTH + tid;
        float s = 0.f;
#pragma unroll
        for (int gc = 0; gc < 32; gc++) s += g_vpart[gc][i];
        g_v[i] = s;
    }
    grid_barrier(1);

    // ---------------- P0c: stage ALL v (128 KB) into smem -----------------
    const float4* gv4 = reinterpret_cast<const float4*>(g_v);
#pragma unroll
    for (int k = 0; k < 8; k++) sv[tid + NTH * k] = gv4[tid + NTH * k];
    __syncthreads();

    // ---------------- P1: energies + per-chunk softmax stats --------------
    // Warp wid owns b = wid. Dynamic tickets balance load across SMs;
    // output & stats are keyed by chunk index -> deterministic.
    {
        const int b = wid;
        const float4* svb = sv + b * 256;

        for (;;) {
            unsigned c;
            if (lane == 0) c = atomicAdd(&g_tick[b], 1u);
            c = __shfl_sync(0xFFFFFFFFu, c, 0);
            if (c >= NCH) break;

            const int l0 = c * CHUNK;
            float m = -INFINITY, s = 0.f;

#pragma unroll 1
            for (int j = 0; j < CHUNK; j++) {
                const float4* e4 = reinterpret_cast<const float4*>(
                    enc + ((size_t)(l0 + j) * B + b) * H);
                float acc = 0.f;
#pragma unroll
                for (int i = 0; i < 8; i++) {
                    float4 a = e4[lane + 32 * i];
                    float4 v = svb[lane + 32 * i];
                    acc = fmaf(a.x, v.x, acc);
                    acc = fmaf(a.y, v.y, acc);
                    acc = fmaf(a.z, v.z, acc);
                    acc = fmaf(a.w, v.w, acc);
                }
#pragma unroll
                for (int off = 16; off; off >>= 1)
                    acc += __shfl_xor_sync(0xFFFFFFFFu, acc, off);

                // online softmax partial (sequential in j -> deterministic)
                if (acc > m) { s = s * __expf(m - acc) + 1.f; m = acc; }
                else         { s += __expf(acc - m); }

                if (lane == 0) g_energies[(size_t)b * L + l0 + j] = acc;
            }
            if (lane == 0) g_cstats[b * NCH + c] = make_float2(m, s);
        }
    }
    grid_barrier(2);

    // ---------------- P2: combine stats + normalize -----------------------
    // (hid.bias term is constant over l -> cancels in softmax -> omitted.)
    if (blk < B) {
        const int b = blk;
        if (tid < 512) s_st[tid] = g_cstats[b * NCH + tid];
        __syncthreads();

        for (int str = 256; str >= 1; str >>= 1) {
            if (tid < str) {
                float2 x = s_st[tid], y = s_st[tid + str];
                float M = fmaxf(x.x, y.x);
                s_st[tid] = make_float2(
                    M, x.y * __expf(x.x - M) + y.y * __expf(y.x - M));
            }
            __syncthreads();
        }
        const float M    = s_st[0].x;
        const float invS = 1.f / s_st[0].y;

#pragma unroll
        for (int k = 0; k < 4; k++) {
            const int idx = tid + NTH * k;
            out[(size_t)b * L + idx] =
                __expf(g_energies[(size_t)b * L + idx] - M) * invS;
        }
    }
}

// ---------------------------------------------------------------------------
// Launch. Inputs (metadata order): hidden [1,B,H], encoder_outputs [L,B,H],
// W [H,H], b [H]. Output: [B,1,L] float32.
// ---------------------------------------------------------------------------
extern "C" void kernel_launch(void* const* d_in, const int* in_sizes, int n_in,
                              void* d_out, int out_size)
{
    const float* hid = (const float*)d_in[0];
    const float* enc = (const float*)d_in[1];
    const float* W   = (const float*)d_in[2];
    // d_in[3] (bias) cancels in softmax -> unused.
    float* out = (float*)d_out;

    // Function-level attribute (persists; first set happens on the
    // pre-capture correctness call). Not a stream op, not an allocation.
    static int attr_done = 0;
    if (!attr_done) {
        cudaFuncSetAttribute(k_fused,
                             cudaFuncAttributeMaxDynamicSharedMemorySize,
                             128 * 1024);
        attr_done = 1;
    }

    k_fused<<<GRID, NTH, 128 * 1024>>>(hid, enc, W, out);
}